// round 15
// baseline (speedup 1.0000x reference)
#include <cuda_runtime.h>
#include <cuda_bf16.h>
#include <cuda_fp16.h>
#include <math.h>
#include <stdint.h>

#define NTOT 32768   // B*H*W = 32*32*32
#define BATCH 32
#define CINN 128
#define COUTN 256
#define MEMN 64

// ---------------- scratch (device globals; allocation-free) ----------------
__device__ float g_bufA[COUTN * NTOT];
__device__ float g_bufB[COUTN * NTOT];
__device__ float g_id[COUTN * NTOT];
__device__ float g_xr[2 * COUTN * NTOT];   // rows 0..255 xf, 256..511 retrieved
__device__ float g_att[MEMN * NTOT];
__device__ float g_sc1[COUTN], g_sh1[COUTN];
__device__ float g_sc2[COUTN], g_sh2[COUTN];
__device__ float g_sc3[COUTN], g_sh3[COUTN];
__device__ float g_av[BATCH * COUTN], g_mx[BATCH * COUTN], g_catt[BATCH * COUTN];
__device__ float g_spm[NTOT], g_spx[NTOT], g_sa[NTOT];

// pre-converted weights (A operands; tiny, converted once)
__device__ __half g_w1h[COUTN * 1152];
__device__ __half g_w2h[COUTN * 2304];
__device__ __half g_wc1h[COUTN * COUTN];
__device__ __half g_wc2h[COUTN * COUTN];
__device__ __half g_wgh[COUTN * 512];
__device__ __half g_mkh[MEMN * COUTN];
__device__ __half g_mth[COUTN * MEMN];
__device__ __nv_bfloat16 g_wsH[COUTN * CINN], g_wsL[COUTN * CINN];

// ---------------- helpers ---------------------------------------------------
__device__ __forceinline__ uint32_t smem_u32(const void* p) {
    uint32_t a;
    asm("{ .reg .u64 t; cvta.to.shared.u64 t, %1; cvt.u32.u64 %0, t; }" : "=r"(a) : "l"(p));
    return a;
}
__device__ __forceinline__ void ldsm4(uint32_t* r, uint32_t addr) {
    asm volatile("ldmatrix.sync.aligned.m8n8.x4.shared.b16 {%0,%1,%2,%3}, [%4];"
                 : "=r"(r[0]), "=r"(r[1]), "=r"(r[2]), "=r"(r[3]) : "r"(addr));
}
__device__ __forceinline__ void mma16816(float* c, const uint32_t* a, const uint32_t* b) {
    asm volatile("mma.sync.aligned.m16n8k16.row.col.f32.bf16.bf16.f32 "
                 "{%0,%1,%2,%3}, {%4,%5,%6,%7}, {%8,%9}, {%0,%1,%2,%3};"
                 : "+f"(c[0]), "+f"(c[1]), "+f"(c[2]), "+f"(c[3])
                 : "r"(a[0]), "r"(a[1]), "r"(a[2]), "r"(a[3]), "r"(b[0]), "r"(b[1]));
}
__device__ __forceinline__ void mma16816h(float* c, const uint32_t* a, const uint32_t* b) {
    asm volatile("mma.sync.aligned.m16n8k16.row.col.f32.f16.f16.f32 "
                 "{%0,%1,%2,%3}, {%4,%5,%6,%7}, {%8,%9}, {%0,%1,%2,%3};"
                 : "+f"(c[0]), "+f"(c[1]), "+f"(c[2]), "+f"(c[3])
                 : "r"(a[0]), "r"(a[1]), "r"(a[2]), "r"(a[3]), "r"(b[0]), "r"(b[1]));
}
__device__ __forceinline__ void split_pack(float a, float b, uint32_t& hp, uint32_t& lp) {
    __nv_bfloat16 ha = __float2bfloat16(a), hb = __float2bfloat16(b);
    float fa = __bfloat162float(ha), fb = __bfloat162float(hb);
    __nv_bfloat16 la = __float2bfloat16(a - fa), lb = __float2bfloat16(b - fb);
    __nv_bfloat162 h2 = __halves2bfloat162(ha, hb);
    __nv_bfloat162 l2 = __halves2bfloat162(la, lb);
    hp = *reinterpret_cast<uint32_t*>(&h2);
    lp = *reinterpret_cast<uint32_t*>(&l2);
}
__device__ __forceinline__ void fsplit(float v, __nv_bfloat16& h, __nv_bfloat16& l) {
    h = __float2bfloat16(v);
    l = __float2bfloat16(v - __bfloat162float(h));
}
__device__ __forceinline__ uint32_t packh2(float a, float b) {
    __half2 h = __halves2half2(__float2half(a), __float2half(b));
    return *reinterpret_cast<uint32_t*>(&h);
}

// ---------------- HMMA GEMM: C[m][n] = sum_k A[m][k]*B_src[k][n] ------------
// Tile 256(m) x 128(n), BK=64, 512 threads, 16 warps = 4(m) x 4(n),
// warp tile 64x32 via m16n8k16. Single m-tile => each B element filled ONCE.
// A operand pre-converted (fp16, or bf16 hi/lo for EMU) => A fill is pure copies.
// SMEM [row][k], stride LDP=80, XOR-16B swizzle (koff ^= (row&7)<<3).
// BMODE: 0 plain [K][NTOT]; 1 im2col3x3 NCHW (CIN=128);
//        2 im2col3x3 [C][NTOT] + fused BN+ReLU (CIN=256); 3 1x1 NCHW (CIN=128)
#define LDP 80
#define SMEM_EMU ((2 * 256 + 2 * 128) * LDP * 2 + 2048)  // 124928
#define SMEM_F16 ((256 + 128) * LDP * 2 + 2048)          // 63488

template <int BMODE, int KTOT, bool EMU, bool RELU, bool HASBIAS>
__global__ __launch_bounds__(512, 1)
void mm_kernel(const void* __restrict__ Ah_, const void* __restrict__ Al_,
               const float* __restrict__ Bsrc,
               float* __restrict__ C, const float* __restrict__ bias,
               const float* __restrict__ bn_s, const float* __restrict__ bn_t, int M)
{
    extern __shared__ __align__(16) char smem[];
    __nv_bfloat16* sAH = (__nv_bfloat16*)smem;
    __nv_bfloat16* sAL = sAH + 256 * LDP;
    __nv_bfloat16* sBH = EMU ? (sAL + 256 * LDP) : sAL;
    __nv_bfloat16* sBL = sBH + 128 * LDP;
    float* s_bns = (float*)(EMU ? (void*)(sBL + 128 * LDP) : (void*)(sBH + 128 * LDP));
    float* s_bnt = s_bns + 256;

    const int tid = threadIdx.x;
    const int wid = tid >> 5, lane = tid & 31;
    const int n0 = blockIdx.y * 128;
    const int wm = wid >> 2, wn = wid & 3;              // warp tile: 64 x 32

    if (BMODE == 2) {
        if (tid < 256) {
            s_bns[tid] = bn_s[tid];
            s_bnt[tid] = bn_t[tid];
        }
        __syncthreads();
    }

    float acc[4][4][4];
#pragma unroll
    for (int i = 0; i < 4; i++)
#pragma unroll
        for (int j = 0; j < 4; j++)
#pragma unroll
            for (int q = 0; q < 4; q++) acc[i][j][q] = 0.f;

    const int b_img = n0 >> 10;
    const int pos0 = n0 & 1023;
    const int h0 = pos0 >> 5;

    const uint32_t aAH = smem_u32(sAH), aAL = smem_u32(sAL);
    const uint32_t aBH = smem_u32(sBH), aBL = smem_u32(sBL);

    const int a_r = lane & 15, a_c = (lane >> 4) << 3;                 // A x4
    const int b_row = ((lane >> 4) << 3) + (lane & 7);                 // n within 16
    const int b_col = (lane & 8);                                      // k half
    const int a_sw = (a_r & 7) << 3;                                   // ldsm A swizzle
    const int b_sw = (lane & 7) << 3;                                  // ldsm B swizzle

    const uint16_t* Ah16 = (const uint16_t*)Ah_;
    const uint16_t* Al16 = (const uint16_t*)Al_;

    for (int k0 = 0; k0 < KTOT; k0 += 64) {
        // ---- A tile: [256 rows][64 k], pre-converted 16-bit, pure copies ----
#pragma unroll
        for (int l = 0; l < 4; l++) {
            int idx = tid + l * 512;            // 2048 uint4 (8 halves each)
            int row = idx >> 3;                 // 0..255
            int q8 = (idx & 7) << 3;            // 0..56 halves
            uint4 vh = make_uint4(0, 0, 0, 0);
            if (row < M)
                vh = *reinterpret_cast<const uint4*>(Ah16 + (size_t)row * KTOT + k0 + q8);
            int off = row * LDP + (q8 ^ ((row & 7) << 3));
            *reinterpret_cast<uint4*>(sAH + off) = vh;
            if (EMU) {
                uint4 vl = make_uint4(0, 0, 0, 0);
                if (row < M)
                    vl = *reinterpret_cast<const uint4*>(Al16 + (size_t)row * KTOT + k0 + q8);
                *reinterpret_cast<uint4*>(sAL + off) = vl;
            }
        }
        // ---- B tile: [n 128][k 64] ----
        if (BMODE == 0 || BMODE == 3) {
#pragma unroll
            for (int l = 0; l < 8; l++) {
                int idx = tid + l * 512;        // 4096 k-pairs
                int nloc = idx & 127;
                int k2 = (idx >> 7) << 1;
                float v0, v1;
                if (BMODE == 0) {
                    const float* p = Bsrc + (size_t)(k0 + k2) * NTOT + n0 + nloc;
                    v0 = p[0]; v1 = p[NTOT];
                } else {
                    const float* p = Bsrc + (((size_t)(b_img * CINN + k0 + k2)) << 10) + pos0 + nloc;
                    v0 = p[0]; v1 = p[1024];
                }
                int off = nloc * LDP + (k2 ^ ((nloc & 7) << 3));
                if (EMU) {
                    uint32_t hp, lp;
                    split_pack(v0, v1, hp, lp);
                    *reinterpret_cast<uint32_t*>(sBH + off) = hp;
                    *reinterpret_cast<uint32_t*>(sBL + off) = lp;
                } else {
                    *reinterpret_cast<uint32_t*>(sBH + off) = packh2(v0, v1);
                }
            }
        } else {
#pragma unroll
            for (int l = 0; l < 16; l++) {
                int idx = tid + l * 512;        // 8192 elements
                int kr = idx >> 7;
                int nloc = idx & 127;
                int kg = k0 + kr;
                int ci = kg / 9;
                int rs = kg - ci * 9;
                int r = rs / 3;
                int s = rs - r * 3;
                int hh = h0 + (nloc >> 5) + r - 1;
                int ww = (nloc & 31) + s - 1;
                float v = 0.f;
                if ((unsigned)hh < 32u && (unsigned)ww < 32u) {
                    if (BMODE == 1) {
                        v = Bsrc[(((size_t)(b_img * CINN + ci)) << 10) + (hh << 5) + ww];
                    } else {
                        float rv = Bsrc[(size_t)ci * NTOT + (b_img << 10) + (hh << 5) + ww];
                        v = fmaxf(fmaf(rv, s_bns[ci], s_bnt[ci]), 0.f);
                    }
                }
                int off = nloc * LDP + (kr ^ ((nloc & 7) << 3));
                *reinterpret_cast<__half*>(sBH + off) = __float2half(v);
            }
        }
        __syncthreads();

        // ---- compute: 4 k16 steps ----
#pragma unroll
        for (int kk = 0; kk < 4; kk++) {
            const int kb = kk * 16;
            if (EMU) {
                uint32_t ah[4][4], al[4][4];
#pragma unroll
                for (int mi = 0; mi < 4; mi++) {
                    uint32_t off = (uint32_t)(((wm * 64 + mi * 16 + a_r) * LDP + ((kb + a_c) ^ a_sw)) * 2);
                    ldsm4(ah[mi], aAH + off);
                    ldsm4(al[mi], aAL + off);
                }
#pragma unroll
                for (int nh = 0; nh < 2; nh++) {
                    uint32_t boff = (uint32_t)(((wn * 32 + nh * 16 + b_row) * LDP + ((kb + b_col) ^ b_sw)) * 2);
                    uint32_t bh[4], bl[4];
                    ldsm4(bh, aBH + boff);
                    ldsm4(bl, aBL + boff);
#pragma unroll
                    for (int mi = 0; mi < 4; mi++) {
                        mma16816(acc[mi][nh * 2 + 0], ah[mi], bh);
                        mma16816(acc[mi][nh * 2 + 1], ah[mi], bh + 2);
                        mma16816(acc[mi][nh * 2 + 0], al[mi], bh);
                        mma16816(acc[mi][nh * 2 + 1], al[mi], bh + 2);
                        mma16816(acc[mi][nh * 2 + 0], ah[mi], bl);
                        mma16816(acc[mi][nh * 2 + 1], ah[mi], bl + 2);
                    }
                }
            } else {
                uint32_t ah[4][4];
#pragma unroll
                for (int mi = 0; mi < 4; mi++) {
                    uint32_t off = (uint32_t)(((wm * 64 + mi * 16 + a_r) * LDP + ((kb + a_c) ^ a_sw)) * 2);
                    ldsm4(ah[mi], aAH + off);
                }
#pragma unroll
                for (int nh = 0; nh < 2; nh++) {
                    uint32_t boff = (uint32_t)(((wn * 32 + nh * 16 + b_row) * LDP + ((kb + b_col) ^ b_sw)) * 2);
                    uint32_t bh[4];
                    ldsm4(bh, aBH + boff);
#pragma unroll
                    for (int mi = 0; mi < 4; mi++) {
                        mma16816h(acc[mi][nh * 2 + 0], ah[mi], bh);
                        mma16816h(acc[mi][nh * 2 + 1], ah[mi], bh + 2);
                    }
                }
            }
        }
        __syncthreads();
    }

    // ---- epilogue ----
    const int tg = lane >> 2, tq = lane & 3;
#pragma unroll
    for (int mi = 0; mi < 4; mi++) {
        int mA = wm * 64 + mi * 16 + tg;
        int mB = mA + 8;
        float bvA = 0.f, bvB = 0.f;
        if (HASBIAS) {
            if (mA < M) bvA = bias[mA];
            if (mB < M) bvB = bias[mB];
        }
#pragma unroll
        for (int ni = 0; ni < 4; ni++) {
            int n = n0 + wn * 32 + ni * 8 + tq * 2;
            if (mA < M) {
                float2 o;
                o.x = acc[mi][ni][0] + bvA;
                o.y = acc[mi][ni][1] + bvA;
                if (RELU) { o.x = fmaxf(o.x, 0.f); o.y = fmaxf(o.y, 0.f); }
                *reinterpret_cast<float2*>(C + (size_t)mA * NTOT + n) = o;
            }
            if (mB < M) {
                float2 o;
                o.x = acc[mi][ni][2] + bvB;
                o.y = acc[mi][ni][3] + bvB;
                if (RELU) { o.x = fmaxf(o.x, 0.f); o.y = fmaxf(o.y, 0.f); }
                *reinterpret_cast<float2*>(C + (size_t)mB * NTOT + n) = o;
            }
        }
    }
}

// ---------------- weight converters -----------------------------------------
__global__ void cvt_half_kernel(const float* __restrict__ src, __half* __restrict__ dst, int n4)
{
    for (int i = blockIdx.x * blockDim.x + threadIdx.x; i < n4; i += gridDim.x * blockDim.x) {
        float4 v = reinterpret_cast<const float4*>(src)[i];
        uint32_t* p = reinterpret_cast<uint32_t*>(dst + i * 4);
        p[0] = packh2(v.x, v.y);
        p[1] = packh2(v.z, v.w);
    }
}
__global__ void cvt_split_kernel(const float* __restrict__ src,
                                 __nv_bfloat16* __restrict__ h, __nv_bfloat16* __restrict__ l, int n)
{
    for (int i = blockIdx.x * blockDim.x + threadIdx.x; i < n; i += gridDim.x * blockDim.x) {
        __nv_bfloat16 hv, lv;
        fsplit(src[i], hv, lv);
        h[i] = hv; l[i] = lv;
    }
}
// mem [64][256] fp32 -> memT [256][64] half
__global__ void memT_cvt_kernel(const float* __restrict__ mem, __half* __restrict__ dst)
{
    int idx = blockIdx.x * blockDim.x + threadIdx.x;   // 16384
    int c = idx >> 6, m = idx & 63;
    dst[idx] = __float2half(mem[m * COUTN + c]);
}

// ---------------- BN statistics (512 threads) -------------------------------
__global__ void bn_stats_kernel(const float* __restrict__ data,
                                const float* __restrict__ gamma,
                                const float* __restrict__ beta,
                                float* __restrict__ scale, float* __restrict__ shift)
{
    const int c = blockIdx.x;
    const int tid = threadIdx.x;
    const float4* p = reinterpret_cast<const float4*>(data + (size_t)c * NTOT);
    float s = 0.f, s2 = 0.f;
    for (int i = tid; i < NTOT / 4; i += 512) {
        float4 v = p[i];
        s += v.x + v.y + v.z + v.w;
        s2 = fmaf(v.x, v.x, s2); s2 = fmaf(v.y, v.y, s2);
        s2 = fmaf(v.z, v.z, s2); s2 = fmaf(v.w, v.w, s2);
    }
    __shared__ float sh1[512], sh2[512];
    sh1[tid] = s; sh2[tid] = s2;
    __syncthreads();
    for (int off = 256; off > 0; off >>= 1) {
        if (tid < off) { sh1[tid] += sh1[tid + off]; sh2[tid] += sh2[tid + off]; }
        __syncthreads();
    }
    if (tid == 0) {
        float mean = sh1[0] * (1.f / NTOT);
        float var = sh2[0] * (1.f / NTOT) - mean * mean;
        float sc = gamma[c] * rsqrtf(var + 1e-5f);
        scale[c] = sc;
        shift[c] = beta[c] - mean * sc;
    }
}

// ---------------- channel pooling -------------------------------------------
__global__ void ch_pool_kernel(const float* __restrict__ c2,
                               const float* __restrict__ scale, const float* __restrict__ shift,
                               float* __restrict__ av, float* __restrict__ mx)
{
    const int b = blockIdx.x, c = blockIdx.y, tid = threadIdx.x;
    const float* p = c2 + (size_t)c * NTOT + (b << 10);
    const float sc = scale[c], sf = shift[c];
    float s = 0.f, m = -3.4e38f;
    for (int i = tid; i < 1024; i += 128) {
        float v = fmaf(p[i], sc, sf);
        s += v;
        m = fmaxf(m, v);
    }
    __shared__ float sh1[128], sh2[128];
    sh1[tid] = s; sh2[tid] = m;
    __syncthreads();
    for (int off = 64; off > 0; off >>= 1) {
        if (tid < off) { sh1[tid] += sh1[tid + off]; sh2[tid] = fmaxf(sh2[tid], sh2[tid + off]); }
        __syncthreads();
    }
    if (tid == 0) {
        av[b * COUTN + c] = sh1[0] * (1.f / 1024.f);
        mx[b * COUTN + c] = sh2[0];
    }
}

// ---------------- channel-attention MLP -------------------------------------
__global__ void ca_mlp_kernel(const float* __restrict__ av, const float* __restrict__ mx,
                              const float* __restrict__ w1, const float* __restrict__ w2,
                              float* __restrict__ catt)
{
    const int b = blockIdx.x, tid = threadIdx.x;
    __shared__ float sav[256], smx[256], ssum[16];
    sav[tid] = av[b * COUTN + tid];
    smx[tid] = mx[b * COUTN + tid];
    __syncthreads();
    if (tid < 16) {
        float ha = 0.f, hm = 0.f;
        for (int c = 0; c < 256; c++) {
            float w = w1[tid * 256 + c];
            ha = fmaf(w, sav[c], ha);
            hm = fmaf(w, smx[c], hm);
        }
        ssum[tid] = fmaxf(ha, 0.f) + fmaxf(hm, 0.f);
    }
    __syncthreads();
    float a = 0.f;
#pragma unroll
    for (int j = 0; j < 16; j++) a = fmaf(w2[tid * 16 + j], ssum[j], a);
    catt[b * COUTN + tid] = 1.f / (1.f + expf(-a));
}

// ---------------- spatial pooling (grid 32 x 8, 128 threads) ----------------
__global__ void sp_pool_kernel(const float* __restrict__ c2,
                               const float* __restrict__ scale, const float* __restrict__ shift,
                               const float* __restrict__ catt,
                               float* __restrict__ spm, float* __restrict__ spx)
{
    const int b = blockIdx.x, pg = blockIdx.y, tid = threadIdx.x;
    __shared__ float sA[256], sB[256];
    {
        float ca0 = catt[b * COUTN + tid];
        float ca1 = catt[b * COUTN + tid + 128];
        sA[tid] = scale[tid] * ca0;
        sB[tid] = shift[tid] * ca0;
        sA[tid + 128] = scale[tid + 128] * ca1;
        sB[tid + 128] = shift[tid + 128] * ca1;
    }
    __syncthreads();
    const int pos = pg * 128 + tid;
    const float* p = c2 + (b << 10) + pos;
    float sm = 0.f, sx = -3.4e38f;
    for (int c = 0; c < 256; c++) {
        float v = fmaf(p[(size_t)c * NTOT], sA[c], sB[c]);
        sm += v;
        sx = fmaxf(sx, v);
    }
    spm[(b << 10) + pos] = sm * (1.f / 256.f);
    spx[(b << 10) + pos] = sx;
}

// ---------------- 7x7 spatial-attention conv --------------------------------
__global__ void sa_conv_kernel(const float* __restrict__ spm, const float* __restrict__ spx,
                               const float* __restrict__ sa_w, const float* __restrict__ sa_b,
                               float* __restrict__ sa)
{
    const int b = blockIdx.x, tid = threadIdx.x;
    __shared__ float pm[1024], px[1024], w[98];
#pragma unroll
    for (int q = 0; q < 4; q++) {
        pm[tid + q * 256] = spm[(b << 10) + tid + q * 256];
        px[tid + q * 256] = spx[(b << 10) + tid + q * 256];
    }
    if (tid < 98) w[tid] = sa_w[tid];
    __syncthreads();
    const float bias = sa_b[0];
#pragma unroll
    for (int q = 0; q < 4; q++) {
        int pos = tid + q * 256;
        int h = pos >> 5, ww = pos & 31;
        float acc = bias;
        for (int r = 0; r < 7; r++) {
            int hh = h + r - 3;
            if ((unsigned)hh >= 32u) continue;
            for (int s = 0; s < 7; s++) {
                int www = ww + s - 3;
                if ((unsigned)www >= 32u) continue;
                acc = fmaf(w[r * 7 + s], pm[(hh << 5) + www], acc);
                acc = fmaf(w[49 + r * 7 + s], px[(hh << 5) + www], acc);
            }
        }
        sa[(b << 10) + pos] = 1.f / (1.f + expf(-acc));
    }
}

// ---------------- xf = bn2(conv2) * ch_att * sp_att -------------------------
__global__ void xf_kernel(const float* __restrict__ c2,
                          const float* __restrict__ scale, const float* __restrict__ shift,
                          const float* __restrict__ catt, const float* __restrict__ sa,
                          float* __restrict__ xr)
{
    const int n4 = COUTN * NTOT / 4;
    for (int i = blockIdx.x * blockDim.x + threadIdx.x; i < n4; i += gridDim.x * blockDim.x) {
        int idx = i * 4;
        int c = idx >> 15;
        int n = idx & 32767;
        int b = n >> 10;
        float s = scale[c], t = shift[c];
        float ca = catt[b * COUTN + c];
        float4 v = reinterpret_cast<const float4*>(c2)[i];
        float4 sv = reinterpret_cast<const float4*>(sa)[n >> 2];
        v.x = fmaf(v.x, s, t) * ca * sv.x;
        v.y = fmaf(v.y, s, t) * ca * sv.y;
        v.z = fmaf(v.z, s, t) * ca * sv.z;
        v.w = fmaf(v.w, s, t) * ca * sv.w;
        reinterpret_cast<float4*>(xr)[i] = v;
    }
}

// ---------------- softmax over 64 memory slots ------------------------------
__global__ void softmax_kernel(float* __restrict__ att)
{
    int n = blockIdx.x * blockDim.x + threadIdx.x;
    float l[64];
    float mx = -3.4e38f;
#pragma unroll
    for (int m = 0; m < 64; m++) {
        l[m] = att[(size_t)m * NTOT + n] * 0.0625f;
        mx = fmaxf(mx, l[m]);
    }
    float s = 0.f;
#pragma unroll
    for (int m = 0; m < 64; m++) {
        l[m] = expf(l[m] - mx);
        s += l[m];
    }
    float inv = 1.f / s;
#pragma unroll
    for (int m = 0; m < 64; m++) att[(size_t)m * NTOT + n] = l[m] * inv;
}

// ---------------- final: gate mix, spike, shortcut BN, relu -----------------
__global__ void final_kernel(const float* __restrict__ gpre, const float* __restrict__ xr,
                             const float* __restrict__ idraw,
                             const float* __restrict__ sc_s, const float* __restrict__ sc_t,
                             float* __restrict__ out)
{
    const int n4 = COUTN * NTOT / 4;
    for (int i = blockIdx.x * blockDim.x + threadIdx.x; i < n4; i += gridDim.x * blockDim.x) {
        int idx = i * 4;
        int c = idx >> 15;
        int n = idx & 32767;
        float s = sc_s[c], t = sc_t[c];
        float4 xf4 = reinterpret_cast<const float4*>(xr)[i];
        float4 rv4 = reinterpret_cast<const float4*>(xr + (size_t)COUTN * NTOT)[i];
        float4 g4 = reinterpret_cast<const float4*>(gpre)[i];
        float4 id4 = reinterpret_cast<const float4*>(idraw)[i];
        float4 o;
#pragma unroll
        for (int q = 0; q < 4; q++) {
            float xfv = (&xf4.x)[q], rv = (&rv4.x)[q];
            float g = 1.f / (1.f + expf(-(&g4.x)[q]));
            float mo = g * rv + (1.f - g) * xfv;
            float spike = (0.1f * mo >= 1.0f) ? 1.f : 0.f;
            float idn = fmaf((&id4.x)[q], s, t);
            (&o.x)[q] = fmaxf(spike + idn, 0.f);
        }
        int b = n >> 10, pos = n & 1023;
        reinterpret_cast<float4*>(out + (((size_t)(b * COUTN + c)) << 10) + pos)[0] = o;
    }
}

// ---------------- launch ----------------------------------------------------
extern "C" void kernel_launch(void* const* d_in, const int* in_sizes, int n_in,
                              void* d_out, int out_size)
{
    const float* x        = (const float*)d_in[0];
    const float* conv1_w  = (const float*)d_in[1];
    const float* conv1_b  = (const float*)d_in[2];
    const float* bn1_g    = (const float*)d_in[3];
    const float* bn1_b    = (const float*)d_in[4];
    const float* conv2_w  = (const float*)d_in[5];
    const float* conv2_b  = (const float*)d_in[6];
    const float* bn2_g    = (const float*)d_in[7];
    const float* bn2_b    = (const float*)d_in[8];
    const float* ca_w1    = (const float*)d_in[9];
    const float* ca_w2    = (const float*)d_in[10];
    const float* sa_w     = (const float*)d_in[11];
    const float* sa_b     = (const float*)d_in[12];
    const float* mem      = (const float*)d_in[13];
    const float* mem_keys = (const float*)d_in[14];
    const float* ctrl_w1  = (const float*)d_in[15];
    const float* ctrl_b1  = (const float*)d_in[16];
    const float* ctrl_w2  = (const float*)d_in[17];
    const float* ctrl_b2  = (const float*)d_in[18];
    const float* gate_w   = (const float*)d_in[19];
    const float* gate_b   = (const float*)d_in[20];
    const float* sc_w     = (const float*)d_in[21];
    const float* sc_g     = (const float*)d_in[22];
    const float* sc_b     = (const float*)d_in[23];
    float* out = (float*)d_out;

    float *bufA, *bufB, *idb, *xr, *att;
    float *sc1, *sh1, *sc2, *sh2, *sc3, *sh3;
    float *av, *mx, *catt, *spm, *spx, *sa;
    __half *w1h, *w2h, *wc1h, *wc2h, *wgh, *mkh, *mth;
    __nv_bfloat16 *wsH, *wsL;
    cudaGetSymbolAddress((void**)&bufA, g_bufA);
    cudaGetSymbolAddress((void**)&bufB, g_bufB);
    cudaGetSymbolAddress((void**)&idb,  g_id);
    cudaGetSymbolAddress((void**)&xr,   g_xr);
    cudaGetSymbolAddress((void**)&att,  g_att);
    cudaGetSymbolAddress((void**)&sc1,  g_sc1);
    cudaGetSymbolAddress((void**)&sh1,  g_sh1);
    cudaGetSymbolAddress((void**)&sc2,  g_sc2);
    cudaGetSymbolAddress((void**)&sh2,  g_sh2);
    cudaGetSymbolAddress((void**)&sc3,  g_sc3);
    cudaGetSymbolAddress((void**)&sh3,  g_sh3);
    cudaGetSymbolAddress((void**)&av,   g_av);
    cudaGetSymbolAddress((void**)&mx,   g_mx);
    cudaGetSymbolAddress((void**)&catt, g_catt);
    cudaGetSymbolAddress((void**)&spm,  g_spm);
    cudaGetSymbolAddress((void**)&spx,  g_spx);
    cudaGetSymbolAddress((void**)&sa,   g_sa);
    cudaGetSymbolAddress((void**)&w1h,  g_w1h);
    cudaGetSymbolAddress((void**)&w2h,  g_w2h);
    cudaGetSymbolAddress((void**)&wc1h, g_wc1h);
    cudaGetSymbolAddress((void**)&wc2h, g_wc2h);
    cudaGetSymbolAddress((void**)&wgh,  g_wgh);
    cudaGetSymbolAddress((void**)&mkh,  g_mkh);
    cudaGetSymbolAddress((void**)&mth,  g_mth);
    cudaGetSymbolAddress((void**)&wsH,  g_wsH);
    cudaGetSymbolAddress((void**)&wsL,  g_wsL);

    cudaFuncSetAttribute((const void*)mm_kernel<1, 1152, false, false, true >, cudaFuncAttributeMaxDynamicSharedMemorySize, SMEM_F16);
    cudaFuncSetAttribute((const void*)mm_kernel<2, 2304, false, false, true >, cudaFuncAttributeMaxDynamicSharedMemorySize, SMEM_F16);
    cudaFuncSetAttribute((const void*)mm_kernel<3, 128,  true,  false, false>, cudaFuncAttributeMaxDynamicSharedMemorySize, SMEM_EMU);
    cudaFuncSetAttribute((const void*)mm_kernel<0, 256,  false, true,  true >, cudaFuncAttributeMaxDynamicSharedMemorySize, SMEM_F16);
    cudaFuncSetAttribute((const void*)mm_kernel<0, 256,  false, false, true >, cudaFuncAttributeMaxDynamicSharedMemorySize, SMEM_F16);
    cudaFuncSetAttribute((const void*)mm_kernel<0, 256,  false, false, false>, cudaFuncAttributeMaxDynamicSharedMemorySize, SMEM_F16);
    cudaFuncSetAttribute((const void*)mm_kernel<0, 64,   false, false, false>, cudaFuncAttributeMaxDynamicSharedMemorySize, SMEM_F16);
    cudaFuncSetAttribute((const void*)mm_kernel<0, 512,  false, false, true >, cudaFuncAttributeMaxDynamicSharedMemorySize, SMEM_F16);

    const dim3 gFull(1, 256);   // single 256-row m tile, 256 n tiles of 128

    // weight conversions (tiny, once)
    cvt_half_kernel<<<144, 256>>>(conv1_w, w1h, COUTN * 1152 / 4);
    cvt_half_kernel<<<288, 256>>>(conv2_w, w2h, COUTN * 2304 / 4);
    cvt_half_kernel<<<64, 256>>>(ctrl_w1, wc1h, COUTN * COUTN / 4);
    cvt_half_kernel<<<64, 256>>>(ctrl_w2, wc2h, COUTN * COUTN / 4);
    cvt_half_kernel<<<128, 256>>>(gate_w, wgh, COUTN * 512 / 4);
    cvt_half_kernel<<<16, 256>>>(mem_keys, mkh, MEMN * COUTN / 4);
    memT_cvt_kernel<<<64, 256>>>(mem, mth);
    cvt_split_kernel<<<128, 256>>>(sc_w, wsH, wsL, COUTN * CINN);

    // conv1 (+bias), fp16 MMA
    mm_kernel<1, 1152, false, false, true><<<gFull, 512, SMEM_F16>>>(w1h, nullptr, x, bufA, conv1_b, nullptr, nullptr, 256);
    bn_stats_kernel<<<256, 512>>>(bufA, bn1_g, bn1_b, sc1, sh1);
    // shortcut 1x1 (bf16x3 — output-critical identity)
    mm_kernel<3, 128, true, false, false><<<gFull, 512, SMEM_EMU>>>(wsH, wsL, x, idb, nullptr, nullptr, nullptr, 256);
    bn_stats_kernel<<<256, 512>>>(idb, sc_g, sc_b, sc3, sh3);
    // conv2 with fused BN1+ReLU on im2col load
    mm_kernel<2, 2304, false, false, true><<<gFull, 512, SMEM_F16>>>(w2h, nullptr, bufA, bufB, conv2_b, sc1, sh1, 256);
    bn_stats_kernel<<<256, 512>>>(bufB, bn2_g, bn2_b, sc2, sh2);
    // channel attention
    ch_pool_kernel<<<dim3(32, 256), 128>>>(bufB, sc2, sh2, av, mx);
    ca_mlp_kernel<<<32, 256>>>(av, mx, ca_w1, ca_w2, catt);
    // spatial attention
    sp_pool_kernel<<<dim3(32, 8), 128>>>(bufB, sc2, sh2, catt, spm, spx);
    sa_conv_kernel<<<32, 256>>>(spm, spx, sa_w, sa_b, sa);
    // xf
    xf_kernel<<<4096, 256>>>(bufB, sc2, sh2, catt, sa, xr);
    // memory module (fp16 MMA)
    mm_kernel<0, 256, false, true,  true ><<<gFull, 512, SMEM_F16>>>(wc1h, nullptr, xr, bufA, ctrl_b1, nullptr, nullptr, 256);
    mm_kernel<0, 256, false, false, true ><<<gFull, 512, SMEM_F16>>>(wc2h, nullptr, bufA, bufB, ctrl_b2, nullptr, nullptr, 256);
    mm_kernel<0, 256, false, false, false><<<gFull, 512, SMEM_F16>>>(mkh, nullptr, bufB, att, nullptr, nullptr, nullptr, 64);
    softmax_kernel<<<128, 256>>>(att);
    mm_kernel<0, 64,  false, false, false><<<gFull, 512, SMEM_F16>>>(mth, nullptr, att, xr + (size_t)COUTN * NTOT, nullptr, nullptr, nullptr, 256);
    mm_kernel<0, 512, false, false, true ><<<gFull, 512, SMEM_F16>>>(wgh, nullptr, xr, bufA, gate_b, nullptr, nullptr, 256);
    // final mix + spike + shortcut + relu
    final_kernel<<<4096, 256>>>(bufA, xr, idb, sc3, sh3, out);
}

// round 17
// speedup vs baseline: 1.3189x; 1.3189x over previous
#include <cuda_runtime.h>
#include <cuda_bf16.h>
#include <cuda_fp16.h>
#include <math.h>
#include <stdint.h>

#define NTOT 32768   // B*H*W = 32*32*32
#define BATCH 32
#define CINN 128
#define COUTN 256
#define MEMN 64

// ---------------- scratch (device globals; allocation-free) ----------------
__device__ float g_bufA[COUTN * NTOT];
__device__ float g_bufB[COUTN * NTOT];
__device__ float g_id[COUTN * NTOT];
__device__ float g_xr[2 * COUTN * NTOT];   // rows 0..255 xf, 256..511 retrieved
__device__ float g_att[MEMN * NTOT];
__device__ float g_sc1[COUTN], g_sh1[COUTN];
__device__ float g_sc2[COUTN], g_sh2[COUTN];
__device__ float g_sc3[COUTN], g_sh3[COUTN];
__device__ float g_av[BATCH * COUTN], g_mx[BATCH * COUTN], g_catt[BATCH * COUTN];
__device__ float g_spm[NTOT], g_spx[NTOT], g_sa[NTOT];
__device__ float g_memT[COUTN * MEMN];

// ---------------- helpers ---------------------------------------------------
__device__ __forceinline__ uint32_t smem_u32(const void* p) {
    uint32_t a;
    asm("{ .reg .u64 t; cvta.to.shared.u64 t, %1; cvt.u32.u64 %0, t; }" : "=r"(a) : "l"(p));
    return a;
}
__device__ __forceinline__ void ldsm4(uint32_t* r, uint32_t addr) {
    asm volatile("ldmatrix.sync.aligned.m8n8.x4.shared.b16 {%0,%1,%2,%3}, [%4];"
                 : "=r"(r[0]), "=r"(r[1]), "=r"(r[2]), "=r"(r[3]) : "r"(addr));
}
__device__ __forceinline__ void mma16816(float* c, const uint32_t* a, const uint32_t* b) {
    asm volatile("mma.sync.aligned.m16n8k16.row.col.f32.bf16.bf16.f32 "
                 "{%0,%1,%2,%3}, {%4,%5,%6,%7}, {%8,%9}, {%0,%1,%2,%3};"
                 : "+f"(c[0]), "+f"(c[1]), "+f"(c[2]), "+f"(c[3])
                 : "r"(a[0]), "r"(a[1]), "r"(a[2]), "r"(a[3]), "r"(b[0]), "r"(b[1]));
}
__device__ __forceinline__ void mma16816h(float* c, const uint32_t* a, const uint32_t* b) {
    asm volatile("mma.sync.aligned.m16n8k16.row.col.f32.f16.f16.f32 "
                 "{%0,%1,%2,%3}, {%4,%5,%6,%7}, {%8,%9}, {%0,%1,%2,%3};"
                 : "+f"(c[0]), "+f"(c[1]), "+f"(c[2]), "+f"(c[3])
                 : "r"(a[0]), "r"(a[1]), "r"(a[2]), "r"(a[3]), "r"(b[0]), "r"(b[1]));
}
__device__ __forceinline__ void split_pack(float a, float b, uint32_t& hp, uint32_t& lp) {
    __nv_bfloat16 ha = __float2bfloat16(a), hb = __float2bfloat16(b);
    float fa = __bfloat162float(ha), fb = __bfloat162float(hb);
    __nv_bfloat16 la = __float2bfloat16(a - fa), lb = __float2bfloat16(b - fb);
    __nv_bfloat162 h2 = __halves2bfloat162(ha, hb);
    __nv_bfloat162 l2 = __halves2bfloat162(la, lb);
    hp = *reinterpret_cast<uint32_t*>(&h2);
    lp = *reinterpret_cast<uint32_t*>(&l2);
}
__device__ __forceinline__ void fsplit(float v, __nv_bfloat16& h, __nv_bfloat16& l) {
    h = __float2bfloat16(v);
    l = __float2bfloat16(v - __bfloat162float(h));
}
__device__ __forceinline__ uint32_t packh2(float a, float b) {
    __half2 h = __halves2half2(__float2half(a), __float2half(b));
    return *reinterpret_cast<uint32_t*>(&h);
}

// ---------------- HMMA GEMM: C[m][n] = sum_k A[m][k]*B_src[k][n] ------------
// Tile 256(m) x 128(n), BK=64, 512 threads, 16 warps = 4(m) x 4(n),
// warp tile 64x32 via m16n8k16.  Single m-tile => each B element filled ONCE.
// EMU=true: bf16x3 emulation (output-critical shortcut). EMU=false: fp16 MMA.
// SMEM [row][k], stride LDP=80, XOR-16B swizzle (koff ^= (row&7)<<3):
// conflict-free STS and ldsm.
// BMODE: 0 plain [K][NTOT]; 1 im2col3x3 NCHW (CIN=128);
//        2 im2col3x3 [C][NTOT] + fused BN+ReLU (CIN=256); 3 1x1 NCHW (CIN=128)
#define LDP 80
#define SMEM_EMU ((2 * 256 + 2 * 128) * LDP * 2 + 2048)  // 124928
#define SMEM_F16 ((256 + 128) * LDP * 2 + 2048)          // 63488

template <int BMODE, int KTOT, bool EMU, bool RELU, bool HASBIAS>
__global__ __launch_bounds__(512, 1)
void mm_kernel(const float* __restrict__ A, const float* __restrict__ Bsrc,
               float* __restrict__ C, const float* __restrict__ bias,
               const float* __restrict__ bn_s, const float* __restrict__ bn_t, int M)
{
    extern __shared__ __align__(16) char smem[];
    // EMU layout: AH[256], AL[256], BH[128], BL[128]. F16: A[256], B[128].
    __nv_bfloat16* sAH = (__nv_bfloat16*)smem;
    __nv_bfloat16* sAL = sAH + 256 * LDP;
    __nv_bfloat16* sBH = EMU ? (sAL + 256 * LDP) : sAL;
    __nv_bfloat16* sBL = sBH + 128 * LDP;
    float* s_bns = (float*)(EMU ? (void*)(sBL + 128 * LDP) : (void*)(sBH + 128 * LDP));
    float* s_bnt = s_bns + 256;

    const int tid = threadIdx.x;
    const int wid = tid >> 5, lane = tid & 31;
    const int n0 = blockIdx.y * 128;
    const int wm = wid >> 2, wn = wid & 3;              // warp tile: 64 x 32

    if (BMODE == 2) {
        if (tid < 256) {
            s_bns[tid] = bn_s[tid];
            s_bnt[tid] = bn_t[tid];
        }
        __syncthreads();
    }

    float acc[4][4][4];
#pragma unroll
    for (int i = 0; i < 4; i++)
#pragma unroll
        for (int j = 0; j < 4; j++)
#pragma unroll
            for (int q = 0; q < 4; q++) acc[i][j][q] = 0.f;

    const int b_img = n0 >> 10;
    const int pos0 = n0 & 1023;
    const int h0 = pos0 >> 5;

    const uint32_t aAH = smem_u32(sAH), aAL = smem_u32(sAL);
    const uint32_t aBH = smem_u32(sBH), aBL = smem_u32(sBL);

    const int a_r = lane & 15, a_c = (lane >> 4) << 3;                 // A x4
    const int b_row = ((lane >> 4) << 3) + (lane & 7);                 // n within 16
    const int b_col = (lane & 8);                                      // k half
    const int a_sw = (a_r & 7) << 3;                                   // ldsm A swizzle
    const int b_sw = (lane & 7) << 3;                                  // ldsm B swizzle

    for (int k0 = 0; k0 < KTOT; k0 += 64) {
        // ---- A tile: [256 rows][64 k] from fp32 weights (4096 quads) ----
#pragma unroll
        for (int l = 0; l < 8; l++) {
            int idx = tid + l * 512;
            int row = idx >> 4;                  // 0..255
            int kq = (idx & 15) << 2;
            float4 v = make_float4(0.f, 0.f, 0.f, 0.f);
            if (row < M)
                v = *reinterpret_cast<const float4*>(A + (size_t)row * KTOT + k0 + kq);
            int off = row * LDP + (kq ^ ((row & 7) << 3));
            if (EMU) {
                uint32_t h01, l01, h23, l23;
                split_pack(v.x, v.y, h01, l01);
                split_pack(v.z, v.w, h23, l23);
                *reinterpret_cast<uint32_t*>(sAH + off)     = h01;
                *reinterpret_cast<uint32_t*>(sAH + off + 2) = h23;
                *reinterpret_cast<uint32_t*>(sAL + off)     = l01;
                *reinterpret_cast<uint32_t*>(sAL + off + 2) = l23;
            } else {
                *reinterpret_cast<uint32_t*>(sAH + off)     = packh2(v.x, v.y);
                *reinterpret_cast<uint32_t*>(sAH + off + 2) = packh2(v.z, v.w);
            }
        }
        // ---- B tile: [n 128][k 64] ----
        if (BMODE == 0 || BMODE == 3) {
#pragma unroll
            for (int l = 0; l < 8; l++) {
                int idx = tid + l * 512;        // 4096 k-pairs
                int nloc = idx & 127;
                int k2 = (idx >> 7) << 1;
                float v0, v1;
                if (BMODE == 0) {
                    const float* p = Bsrc + (size_t)(k0 + k2) * NTOT + n0 + nloc;
                    v0 = p[0]; v1 = p[NTOT];
                } else {
                    const float* p = Bsrc + (((size_t)(b_img * CINN + k0 + k2)) << 10) + pos0 + nloc;
                    v0 = p[0]; v1 = p[1024];
                }
                int off = nloc * LDP + (k2 ^ ((nloc & 7) << 3));
                if (EMU) {
                    uint32_t hp, lp;
                    split_pack(v0, v1, hp, lp);
                    *reinterpret_cast<uint32_t*>(sBH + off) = hp;
                    *reinterpret_cast<uint32_t*>(sBL + off) = lp;
                } else {
                    *reinterpret_cast<uint32_t*>(sBH + off) = packh2(v0, v1);
                }
            }
        } else {
#pragma unroll
            for (int l = 0; l < 16; l++) {
                int idx = tid + l * 512;        // 8192 elements
                int kr = idx >> 7;
                int nloc = idx & 127;
                int kg = k0 + kr;
                int ci = kg / 9;
                int rs = kg - ci * 9;
                int r = rs / 3;
                int s = rs - r * 3;
                int hh = h0 + (nloc >> 5) + r - 1;
                int ww = (nloc & 31) + s - 1;
                float v = 0.f;
                if ((unsigned)hh < 32u && (unsigned)ww < 32u) {
                    if (BMODE == 1) {
                        v = Bsrc[(((size_t)(b_img * CINN + ci)) << 10) + (hh << 5) + ww];
                    } else {
                        float rv = Bsrc[(size_t)ci * NTOT + (b_img << 10) + (hh << 5) + ww];
                        v = fmaxf(fmaf(rv, s_bns[ci], s_bnt[ci]), 0.f);
                    }
                }
                int off = nloc * LDP + (kr ^ ((nloc & 7) << 3));
                if (EMU) {
                    __nv_bfloat16 hb, lb;
                    fsplit(v, hb, lb);
                    sBH[off] = hb;
                    sBL[off] = lb;
                } else {
                    *reinterpret_cast<__half*>(sBH + off) = __float2half(v);
                }
            }
        }
        __syncthreads();

        // ---- compute: 4 k16 steps ----
#pragma unroll
        for (int kk = 0; kk < 4; kk++) {
            const int kb = kk * 16;
            if (EMU) {
                uint32_t ah[4][4], al[4][4];
#pragma unroll
                for (int mi = 0; mi < 4; mi++) {
                    uint32_t off = (uint32_t)(((wm * 64 + mi * 16 + a_r) * LDP + ((kb + a_c) ^ a_sw)) * 2);
                    ldsm4(ah[mi], aAH + off);
                    ldsm4(al[mi], aAL + off);
                }
#pragma unroll
                for (int nh = 0; nh < 2; nh++) {
                    uint32_t boff = (uint32_t)(((wn * 32 + nh * 16 + b_row) * LDP + ((kb + b_col) ^ b_sw)) * 2);
                    uint32_t bh[4], bl[4];
                    ldsm4(bh, aBH + boff);
                    ldsm4(bl, aBL + boff);
#pragma unroll
                    for (int mi = 0; mi < 4; mi++) {
                        mma16816(acc[mi][nh * 2 + 0], ah[mi], bh);
                        mma16816(acc[mi][nh * 2 + 1], ah[mi], bh + 2);
                        mma16816(acc[mi][nh * 2 + 0], al[mi], bh);
                        mma16816(acc[mi][nh * 2 + 1], al[mi], bh + 2);
                        mma16816(acc[mi][nh * 2 + 0], ah[mi], bl);
                        mma16816(acc[mi][nh * 2 + 1], ah[mi], bl + 2);
                    }
                }
            } else {
                uint32_t ah[4][4];
#pragma unroll
                for (int mi = 0; mi < 4; mi++) {
                    uint32_t off = (uint32_t)(((wm * 64 + mi * 16 + a_r) * LDP + ((kb + a_c) ^ a_sw)) * 2);
                    ldsm4(ah[mi], aAH + off);
                }
#pragma unroll
                for (int nh = 0; nh < 2; nh++) {
                    uint32_t boff = (uint32_t)(((wn * 32 + nh * 16 + b_row) * LDP + ((kb + b_col) ^ b_sw)) * 2);
                    uint32_t bh[4];
                    ldsm4(bh, aBH + boff);
#pragma unroll
                    for (int mi = 0; mi < 4; mi++) {
                        mma16816h(acc[mi][nh * 2 + 0], ah[mi], bh);
                        mma16816h(acc[mi][nh * 2 + 1], ah[mi], bh + 2);
                    }
                }
            }
        }
        __syncthreads();
    }

    // ---- epilogue ----
    const int tg = lane >> 2, tq = lane & 3;
#pragma unroll
    for (int mi = 0; mi < 4; mi++) {
        int mA = wm * 64 + mi * 16 + tg;
        int mB = mA + 8;
        float bvA = 0.f, bvB = 0.f;
        if (HASBIAS) {
            if (mA < M) bvA = bias[mA];
            if (mB < M) bvB = bias[mB];
        }
#pragma unroll
        for (int ni = 0; ni < 4; ni++) {
            int n = n0 + wn * 32 + ni * 8 + tq * 2;
            if (mA < M) {
                float2 o;
                o.x = acc[mi][ni][0] + bvA;
                o.y = acc[mi][ni][1] + bvA;
                if (RELU) { o.x = fmaxf(o.x, 0.f); o.y = fmaxf(o.y, 0.f); }
                *reinterpret_cast<float2*>(C + (size_t)mA * NTOT + n) = o;
            }
            if (mB < M) {
                float2 o;
                o.x = acc[mi][ni][2] + bvB;
                o.y = acc[mi][ni][3] + bvB;
                if (RELU) { o.x = fmaxf(o.x, 0.f); o.y = fmaxf(o.y, 0.f); }
                *reinterpret_cast<float2*>(C + (size_t)mB * NTOT + n) = o;
            }
        }
    }
}

// ---------------- tiny warm/no-op kernel (launch-order pad for ncu) ---------
__global__ void warm_kernel(float* p) {
    if (threadIdx.x == 0 && blockIdx.x == 0) p[0] = 0.f;
}

// ---------------- BN statistics ---------------------------------------------
__global__ void bn_stats_kernel(const float* __restrict__ data,
                                const float* __restrict__ gamma,
                                const float* __restrict__ beta,
                                float* __restrict__ scale, float* __restrict__ shift)
{
    const int c = blockIdx.x;
    const int tid = threadIdx.x;
    const float4* p = reinterpret_cast<const float4*>(data + (size_t)c * NTOT);
    float s = 0.f, s2 = 0.f;
    for (int i = tid; i < NTOT / 4; i += 256) {
        float4 v = p[i];
        s += v.x + v.y + v.z + v.w;
        s2 = fmaf(v.x, v.x, s2); s2 = fmaf(v.y, v.y, s2);
        s2 = fmaf(v.z, v.z, s2); s2 = fmaf(v.w, v.w, s2);
    }
    __shared__ float sh1[256], sh2[256];
    sh1[tid] = s; sh2[tid] = s2;
    __syncthreads();
    for (int off = 128; off > 0; off >>= 1) {
        if (tid < off) { sh1[tid] += sh1[tid + off]; sh2[tid] += sh2[tid + off]; }
        __syncthreads();
    }
    if (tid == 0) {
        float mean = sh1[0] * (1.f / NTOT);
        float var = sh2[0] * (1.f / NTOT) - mean * mean;
        float sc = gamma[c] * rsqrtf(var + 1e-5f);
        scale[c] = sc;
        shift[c] = beta[c] - mean * sc;
    }
}

// ---------------- channel pooling -------------------------------------------
__global__ void ch_pool_kernel(const float* __restrict__ c2,
                               const float* __restrict__ scale, const float* __restrict__ shift,
                               float* __restrict__ av, float* __restrict__ mx)
{
    const int b = blockIdx.x, c = blockIdx.y, tid = threadIdx.x;
    const float* p = c2 + (size_t)c * NTOT + (b << 10);
    const float sc = scale[c], sf = shift[c];
    float s = 0.f, m = -3.4e38f;
    for (int i = tid; i < 1024; i += 128) {
        float v = fmaf(p[i], sc, sf);
        s += v;
        m = fmaxf(m, v);
    }
    __shared__ float sh1[128], sh2[128];
    sh1[tid] = s; sh2[tid] = m;
    __syncthreads();
    for (int off = 64; off > 0; off >>= 1) {
        if (tid < off) { sh1[tid] += sh1[tid + off]; sh2[tid] = fmaxf(sh2[tid], sh2[tid + off]); }
        __syncthreads();
    }
    if (tid == 0) {
        av[b * COUTN + c] = sh1[0] * (1.f / 1024.f);
        mx[b * COUTN + c] = sh2[0];
    }
}

// ---------------- channel-attention MLP -------------------------------------
__global__ void ca_mlp_kernel(const float* __restrict__ av, const float* __restrict__ mx,
                              const float* __restrict__ w1, const float* __restrict__ w2,
                              float* __restrict__ catt)
{
    const int b = blockIdx.x, tid = threadIdx.x;
    __shared__ float sav[256], smx[256], ssum[16];
    sav[tid] = av[b * COUTN + tid];
    smx[tid] = mx[b * COUTN + tid];
    __syncthreads();
    if (tid < 16) {
        float ha = 0.f, hm = 0.f;
        for (int c = 0; c < 256; c++) {
            float w = w1[tid * 256 + c];
            ha = fmaf(w, sav[c], ha);
            hm = fmaf(w, smx[c], hm);
        }
        ssum[tid] = fmaxf(ha, 0.f) + fmaxf(hm, 0.f);
    }
    __syncthreads();
    float a = 0.f;
#pragma unroll
    for (int j = 0; j < 16; j++) a = fmaf(w2[tid * 16 + j], ssum[j], a);
    catt[b * COUTN + tid] = 1.f / (1.f + expf(-a));
}

// ---------------- spatial pooling (grid 32 x 8, 128 threads) ----------------
__global__ void sp_pool_kernel(const float* __restrict__ c2,
                               const float* __restrict__ scale, const float* __restrict__ shift,
                               const float* __restrict__ catt,
                               float* __restrict__ spm, float* __restrict__ spx)
{
    const int b = blockIdx.x, pg = blockIdx.y, tid = threadIdx.x;
    __shared__ float sA[256], sB[256];
    {
        float ca0 = catt[b * COUTN + tid];
        float ca1 = catt[b * COUTN + tid + 128];
        sA[tid] = scale[tid] * ca0;
        sB[tid] = shift[tid] * ca0;
        sA[tid + 128] = scale[tid + 128] * ca1;
        sB[tid + 128] = shift[tid + 128] * ca1;
    }
    __syncthreads();
    const int pos = pg * 128 + tid;
    const float* p = c2 + (b << 10) + pos;
    float sm = 0.f, sx = -3.4e38f;
    for (int c = 0; c < 256; c++) {
        float v = fmaf(p[(size_t)c * NTOT], sA[c], sB[c]);
        sm += v;
        sx = fmaxf(sx, v);
    }
    spm[(b << 10) + pos] = sm * (1.f / 256.f);
    spx[(b << 10) + pos] = sx;
}

// ---------------- 7x7 spatial-attention conv --------------------------------
__global__ void sa_conv_kernel(const float* __restrict__ spm, const float* __restrict__ spx,
                               const float* __restrict__ sa_w, const float* __restrict__ sa_b,
                               float* __restrict__ sa)
{
    const int b = blockIdx.x, tid = threadIdx.x;
    __shared__ float pm[1024], px[1024], w[98];
#pragma unroll
    for (int q = 0; q < 4; q++) {
        pm[tid + q * 256] = spm[(b << 10) + tid + q * 256];
        px[tid + q * 256] = spx[(b << 10) + tid + q * 256];
    }
    if (tid < 98) w[tid] = sa_w[tid];
    __syncthreads();
    const float bias = sa_b[0];
#pragma unroll
    for (int q = 0; q < 4; q++) {
        int pos = tid + q * 256;
        int h = pos >> 5, ww = pos & 31;
        float acc = bias;
        for (int r = 0; r < 7; r++) {
            int hh = h + r - 3;
            if ((unsigned)hh >= 32u) continue;
            for (int s = 0; s < 7; s++) {
                int www = ww + s - 3;
                if ((unsigned)www >= 32u) continue;
                acc = fmaf(w[r * 7 + s], pm[(hh << 5) + www], acc);
                acc = fmaf(w[49 + r * 7 + s], px[(hh << 5) + www], acc);
            }
        }
        sa[(b << 10) + pos] = 1.f / (1.f + expf(-acc));
    }
}

// ---------------- xf = bn2(conv2) * ch_att * sp_att -------------------------
__global__ void xf_kernel(const float* __restrict__ c2,
                          const float* __restrict__ scale, const float* __restrict__ shift,
                          const float* __restrict__ catt, const float* __restrict__ sa,
                          float* __restrict__ xr)
{
    const int n4 = COUTN * NTOT / 4;
    for (int i = blockIdx.x * blockDim.x + threadIdx.x; i < n4; i += gridDim.x * blockDim.x) {
        int idx = i * 4;
        int c = idx >> 15;
        int n = idx & 32767;
        int b = n >> 10;
        float s = scale[c], t = shift[c];
        float ca = catt[b * COUTN + c];
        float4 v = reinterpret_cast<const float4*>(c2)[i];
        float4 sv = reinterpret_cast<const float4*>(sa)[n >> 2];
        v.x = fmaf(v.x, s, t) * ca * sv.x;
        v.y = fmaf(v.y, s, t) * ca * sv.y;
        v.z = fmaf(v.z, s, t) * ca * sv.z;
        v.w = fmaf(v.w, s, t) * ca * sv.w;
        reinterpret_cast<float4*>(xr)[i] = v;
    }
}

// ---------------- transpose mem (64x256 -> 256x64) --------------------------
__global__ void memT_kernel(const float* __restrict__ mem, float* __restrict__ memT)
{
    int idx = blockIdx.x * blockDim.x + threadIdx.x;
    int c = idx >> 6, m = idx & 63;
    memT[idx] = mem[m * COUTN + c];
}

// ---------------- softmax over 64 memory slots ------------------------------
__global__ void softmax_kernel(float* __restrict__ att)
{
    int n = blockIdx.x * blockDim.x + threadIdx.x;
    float l[64];
    float mx = -3.4e38f;
#pragma unroll
    for (int m = 0; m < 64; m++) {
        l[m] = att[(size_t)m * NTOT + n] * 0.0625f;
        mx = fmaxf(mx, l[m]);
    }
    float s = 0.f;
#pragma unroll
    for (int m = 0; m < 64; m++) {
        l[m] = expf(l[m] - mx);
        s += l[m];
    }
    float inv = 1.f / s;
#pragma unroll
    for (int m = 0; m < 64; m++) att[(size_t)m * NTOT + n] = l[m] * inv;
}

// ---------------- final: gate mix, spike, shortcut BN, relu -----------------
__global__ void final_kernel(const float* __restrict__ gpre, const float* __restrict__ xr,
                             const float* __restrict__ idraw,
                             const float* __restrict__ sc_s, const float* __restrict__ sc_t,
                             float* __restrict__ out)
{
    const int n4 = COUTN * NTOT / 4;
    for (int i = blockIdx.x * blockDim.x + threadIdx.x; i < n4; i += gridDim.x * blockDim.x) {
        int idx = i * 4;
        int c = idx >> 15;
        int n = idx & 32767;
        float s = sc_s[c], t = sc_t[c];
        float4 xf4 = reinterpret_cast<const float4*>(xr)[i];
        float4 rv4 = reinterpret_cast<const float4*>(xr + (size_t)COUTN * NTOT)[i];
        float4 g4 = reinterpret_cast<const float4*>(gpre)[i];
        float4 id4 = reinterpret_cast<const float4*>(idraw)[i];
        float4 o;
#pragma unroll
        for (int q = 0; q < 4; q++) {
            float xfv = (&xf4.x)[q], rv = (&rv4.x)[q];
            float g = 1.f / (1.f + expf(-(&g4.x)[q]));
            float mo = g * rv + (1.f - g) * xfv;
            float spike = (0.1f * mo >= 1.0f) ? 1.f : 0.f;
            float idn = fmaf((&id4.x)[q], s, t);
            (&o.x)[q] = fmaxf(spike + idn, 0.f);
        }
        int b = n >> 10, pos = n & 1023;
        reinterpret_cast<float4*>(out + (((size_t)(b * COUTN + c)) << 10) + pos)[0] = o;
    }
}

// ---------------- launch ----------------------------------------------------
extern "C" void kernel_launch(void* const* d_in, const int* in_sizes, int n_in,
                              void* d_out, int out_size)
{
    const float* x        = (const float*)d_in[0];
    const float* conv1_w  = (const float*)d_in[1];
    const float* conv1_b  = (const float*)d_in[2];
    const float* bn1_g    = (const float*)d_in[3];
    const float* bn1_b    = (const float*)d_in[4];
    const float* conv2_w  = (const float*)d_in[5];
    const float* conv2_b  = (const float*)d_in[6];
    const float* bn2_g    = (const float*)d_in[7];
    const float* bn2_b    = (const float*)d_in[8];
    const float* ca_w1    = (const float*)d_in[9];
    const float* ca_w2    = (const float*)d_in[10];
    const float* sa_w     = (const float*)d_in[11];
    const float* sa_b     = (const float*)d_in[12];
    const float* mem      = (const float*)d_in[13];
    const float* mem_keys = (const float*)d_in[14];
    const float* ctrl_w1  = (const float*)d_in[15];
    const float* ctrl_b1  = (const float*)d_in[16];
    const float* ctrl_w2  = (const float*)d_in[17];
    const float* ctrl_b2  = (const float*)d_in[18];
    const float* gate_w   = (const float*)d_in[19];
    const float* gate_b   = (const float*)d_in[20];
    const float* sc_w     = (const float*)d_in[21];
    const float* sc_g     = (const float*)d_in[22];
    const float* sc_b     = (const float*)d_in[23];
    float* out = (float*)d_out;

    float *bufA, *bufB, *idb, *xr, *att;
    float *sc1, *sh1, *sc2, *sh2, *sc3, *sh3;
    float *av, *mx, *catt, *spm, *spx, *sa, *memT;
    cudaGetSymbolAddress((void**)&bufA, g_bufA);
    cudaGetSymbolAddress((void**)&bufB, g_bufB);
    cudaGetSymbolAddress((void**)&idb,  g_id);
    cudaGetSymbolAddress((void**)&xr,   g_xr);
    cudaGetSymbolAddress((void**)&att,  g_att);
    cudaGetSymbolAddress((void**)&sc1,  g_sc1);
    cudaGetSymbolAddress((void**)&sh1,  g_sh1);
    cudaGetSymbolAddress((void**)&sc2,  g_sc2);
    cudaGetSymbolAddress((void**)&sh2,  g_sh2);
    cudaGetSymbolAddress((void**)&sc3,  g_sc3);
    cudaGetSymbolAddress((void**)&sh3,  g_sh3);
    cudaGetSymbolAddress((void**)&av,   g_av);
    cudaGetSymbolAddress((void**)&mx,   g_mx);
    cudaGetSymbolAddress((void**)&catt, g_catt);
    cudaGetSymbolAddress((void**)&spm,  g_spm);
    cudaGetSymbolAddress((void**)&spx,  g_spx);
    cudaGetSymbolAddress((void**)&sa,   g_sa);
    cudaGetSymbolAddress((void**)&memT, g_memT);

    cudaFuncSetAttribute((const void*)mm_kernel<1, 1152, false, false, true >, cudaFuncAttributeMaxDynamicSharedMemorySize, SMEM_F16);
    cudaFuncSetAttribute((const void*)mm_kernel<2, 2304, false, false, true >, cudaFuncAttributeMaxDynamicSharedMemorySize, SMEM_F16);
    cudaFuncSetAttribute((const void*)mm_kernel<3, 128,  true,  false, false>, cudaFuncAttributeMaxDynamicSharedMemorySize, SMEM_EMU);
    cudaFuncSetAttribute((const void*)mm_kernel<0, 256,  false, true,  true >, cudaFuncAttributeMaxDynamicSharedMemorySize, SMEM_F16);
    cudaFuncSetAttribute((const void*)mm_kernel<0, 256,  false, false, true >, cudaFuncAttributeMaxDynamicSharedMemorySize, SMEM_F16);
    cudaFuncSetAttribute((const void*)mm_kernel<0, 256,  false, false, false>, cudaFuncAttributeMaxDynamicSharedMemorySize, SMEM_F16);
    cudaFuncSetAttribute((const void*)mm_kernel<0, 64,   false, false, false>, cudaFuncAttributeMaxDynamicSharedMemorySize, SMEM_F16);
    cudaFuncSetAttribute((const void*)mm_kernel<0, 512,  false, false, true >, cudaFuncAttributeMaxDynamicSharedMemorySize, SMEM_F16);

    const dim3 gFull(1, 256);   // single 256-row m tile, 256 n tiles of 128

    // 1: conv1 (+bias), fp16 MMA
    mm_kernel<1, 1152, false, false, true><<<gFull, 512, SMEM_F16>>>(conv1_w, x, bufA, conv1_b, nullptr, nullptr, 256);
    // 2: BN1 stats
    bn_stats_kernel<<<256, 256>>>(bufA, bn1_g, bn1_b, sc1, sh1);
    // 3: shortcut 1x1 (bf16x3 — output-critical identity)
    mm_kernel<3, 128, true, false, false><<<gFull, 512, SMEM_EMU>>>(sc_w, x, idb, nullptr, nullptr, nullptr, 256);
    // 4: shortcut BN stats
    bn_stats_kernel<<<256, 256>>>(idb, sc_g, sc_b, sc3, sh3);
    // 5: warm no-op (pad)
    warm_kernel<<<1, 32>>>(att);
    // 6: conv2 with fused BN1+ReLU on im2col load  <-- ncu capture target
    mm_kernel<2, 2304, false, false, true><<<gFull, 512, SMEM_F16>>>(conv2_w, bufA, bufB, conv2_b, sc1, sh1, 256);
    // BN2 stats
    bn_stats_kernel<<<256, 256>>>(bufB, bn2_g, bn2_b, sc2, sh2);
    // channel attention
    ch_pool_kernel<<<dim3(32, 256), 128>>>(bufB, sc2, sh2, av, mx);
    ca_mlp_kernel<<<32, 256>>>(av, mx, ca_w1, ca_w2, catt);
    // spatial attention (split over 8 position groups)
    sp_pool_kernel<<<dim3(32, 8), 128>>>(bufB, sc2, sh2, catt, spm, spx);
    sa_conv_kernel<<<32, 256>>>(spm, spx, sa_w, sa_b, sa);
    // xf
    xf_kernel<<<4096, 256>>>(bufB, sc2, sh2, catt, sa, xr);
    // memory module (fp16 MMA)
    mm_kernel<0, 256, false, true,  true ><<<gFull, 512, SMEM_F16>>>(ctrl_w1, xr, bufA, ctrl_b1, nullptr, nullptr, 256);
    mm_kernel<0, 256, false, false, true ><<<gFull, 512, SMEM_F16>>>(ctrl_w2, bufA, bufB, ctrl_b2, nullptr, nullptr, 256);
    mm_kernel<0, 256, false, false, false><<<gFull, 512, SMEM_F16>>>(mem_keys, bufB, att, nullptr, nullptr, nullptr, 64);
    softmax_kernel<<<128, 256>>>(att);
    memT_kernel<<<64, 256>>>(mem, memT);
    mm_kernel<0, 64,  false, false, false><<<gFull, 512, SMEM_F16>>>(memT, att, xr + (size_t)COUTN * NTOT, nullptr, nullptr, nullptr, 256);
    mm_kernel<0, 512, false, false, true ><<<gFull, 512, SMEM_F16>>>(gate_w, xr, bufA, gate_b, nullptr, nullptr, 256);
    // final mix + spike + shortcut + relu
    final_kernel<<<4096, 256>>>(bufA, xr, idb, sc3, sh3, out);
}